// round 9
// baseline (speedup 1.0000x reference)
#include <cuda_runtime.h>

// ---------------- problem constants ----------------
#define BATCH 1024
#define C0_ 512
#define C1_ 1024
#define K0_ 100
#define K1_ 50
#define KP0 128
#define KP1 64
#define ROWS0 (BATCH*C0_)   // 524288
#define ROWS1 (BATCH*C1_)   // 1048576

#define MB 16
#define CC 32
#define PITCH0 132
#define PITCH1 68
#define NT0 (BATCH/MB)      // 64 head0 tiles
#define NT1 (BATCH/MB)      // 64 head1 tiles

// pool block classes
#define NB0 (ROWS0/8)       // 65536 pool0 blocks (8 rows each, warp/row)
#define P1_RPB 128
#define P1_FLT (P1_RPB*49)  // 6272
#define P1_VEC (P1_FLT/4)   // 1568
#define NB1 (ROWS1/P1_RPB)  // 8192 pool1 blocks

// grid layout: [0,64) head0 | [64,128) head1 | [128,128+NB0) pool0 | rest pool1
#define HB0 0
#define HB1 64
#define PB0 128
#define PB1 (128+NB0)
#define NBLKS (128+NB0+NB1)

// smem union: head0 27392B (sp 2048 | swt 16896 | slg 8448) >= pool1 25088 >= head1 15104
#define SM_BYTES 27392

// ---------------- device state (zero-init; reset at end of each run) -------
__device__ float    g_pooled0[ROWS0];
__device__ float    g_pooled1[ROWS1];
__device__ float    g_accum[4];
__device__ unsigned g_cnt0[NT0];
__device__ unsigned g_cnt1[NT1];
__device__ unsigned g_done;

// ---------------- doorbell wait ----------------
__device__ __forceinline__ void wait_cnt(volatile unsigned* p, unsigned v) {
    if (threadIdx.x == 0) {
        while (*p < v) __nanosleep(256);
    }
    __syncthreads();
    __threadfence();
}

// ---------------- head tile: smem-tiled GEMM + softmax-CE (CC=32) ----------
template<int C, int K, int KPAD, int TK, int PITCH, int AOFF>
__device__ __forceinline__ void head_tile(
    const float* __restrict__ pooled,
    const float* __restrict__ W, const float* __restrict__ bias,
    const int* __restrict__ lut, const float* __restrict__ cw,
    const int* __restrict__ target, int m0, char* sraw)
{
    float (*sp)[CC]     = reinterpret_cast<float(*)[CC]>(sraw);
    float (*swt)[PITCH] = reinterpret_cast<float(*)[PITCH]>(sraw + 4*MB*CC);
    float (*slg)[PITCH] = reinterpret_cast<float(*)[PITCH]>(sraw + 4*(MB*CC + CC*PITCH));

    const int tid = threadIdx.x;
    const int ktg = tid & 63;
    const int bt  = tid >> 6;

    float acc[4][TK];
    #pragma unroll
    for (int j = 0; j < 4; j++)
        #pragma unroll
        for (int t = 0; t < TK; t++) acc[j][t] = 0.0f;

    for (int c0 = 0; c0 < C; c0 += CC) {
        if (tid < MB * CC / 4) {
            const int row = tid >> 3;         // 0..15
            const int c4  = tid & 7;          // 0..7
            float4 v = *reinterpret_cast<const float4*>(
                pooled + (size_t)(m0 + row) * C + c0 + c4 * 4);
            *reinterpret_cast<float4*>(&sp[row][c4 * 4]) = v;
        }
        #pragma unroll
        for (int idx = tid; idx < KPAD * CC; idx += 256) {
            const int c = idx & (CC - 1);
            const int k = idx >> 5;
            swt[c][k] = (k < K) ? W[(size_t)k * C + c0 + c] : 0.0f;
        }
        __syncthreads();

        #pragma unroll
        for (int c4 = 0; c4 < CC / 4; c4++) {
            float pv[4][4];
            #pragma unroll
            for (int j = 0; j < 4; j++) {
                float4 v = *reinterpret_cast<const float4*>(&sp[bt * 4 + j][c4 * 4]);
                pv[j][0] = v.x; pv[j][1] = v.y; pv[j][2] = v.z; pv[j][3] = v.w;
            }
            #pragma unroll
            for (int cc = 0; cc < 4; cc++) {
                const int c = c4 * 4 + cc;
                if (TK == 2) {
                    float2 wv = *reinterpret_cast<const float2*>(&swt[c][ktg * 2]);
                    #pragma unroll
                    for (int j = 0; j < 4; j++) {
                        acc[j][0] = fmaf(pv[j][cc], wv.x, acc[j][0]);
                        acc[j][1] = fmaf(pv[j][cc], wv.y, acc[j][1]);
                    }
                } else {
                    float wv = swt[c][ktg];
                    #pragma unroll
                    for (int j = 0; j < 4; j++)
                        acc[j][0] = fmaf(pv[j][cc], wv, acc[j][0]);
                }
            }
        }
        __syncthreads();
    }

    #pragma unroll
    for (int t = 0; t < TK; t++) {
        const int k = ktg * TK + t;
        const float bv = (k < K) ? bias[k] : 0.0f;
        #pragma unroll
        for (int j = 0; j < 4; j++)
            slg[bt * 4 + j][k] = acc[j][t] + bv;
    }
    __syncthreads();

    const int w = tid >> 5, lane = tid & 31;
    #pragma unroll
    for (int r = w; r < MB; r += 8) {
        float m = -3.4e38f;
        for (int k = lane; k < K; k += 32) m = fmaxf(m, slg[r][k]);
        #pragma unroll
        for (int o = 16; o; o >>= 1) m = fmaxf(m, __shfl_xor_sync(0xffffffffu, m, o));
        float s = 0.0f;
        for (int k = lane; k < K; k += 32) s += __expf(slg[r][k] - m);
        #pragma unroll
        for (int o = 16; o; o >>= 1) s += __shfl_xor_sync(0xffffffffu, s, o);
        if (lane == 0) {
            const int t = lut[target[m0 + r]];
            const float nll = m + __logf(s) - slg[r][t];
            const float wt  = cw[t];
            atomicAdd(&g_accum[AOFF],     wt * nll);
            atomicAdd(&g_accum[AOFF + 1], wt);
        }
    }
    __syncthreads();
}

// ---------------- the single fused kernel ----------------
__global__ void __launch_bounds__(256, 6)
mega_kernel(const float* __restrict__ feat0, const float* __restrict__ feat1,
            const float* __restrict__ W0, const float* __restrict__ b0v,
            const float* __restrict__ W1, const float* __restrict__ b1v,
            const int* __restrict__ lut0, const int* __restrict__ lut1,
            const float* __restrict__ cw0, const float* __restrict__ cw1,
            const int* __restrict__ target, float* __restrict__ out)
{
    __shared__ __align__(16) char sraw[SM_BYTES];
    const unsigned bx = blockIdx.x;
    const int tid = threadIdx.x;

    if (bx >= PB1) {
        // ---- pool1 block: 128 feat1 rows via smem staging ----
        const unsigned q = bx - PB1;
        float* sf = (float*)sraw;
        const float4* src = reinterpret_cast<const float4*>(feat1) + (size_t)q * P1_VEC;
        float4* dst = reinterpret_cast<float4*>(sf);
        #pragma unroll 4
        for (int i = tid; i < P1_VEC; i += 256)
            dst[i] = __ldcs(src + i);
        __syncthreads();
        if (tid < P1_RPB) {
            const float* r = sf + tid * 49;
            float s0 = 0.f, s1 = 0.f, s2 = 0.f, s3 = 0.f;
            #pragma unroll
            for (int e = 0; e < 48; e += 4) {
                s0 += r[e]; s1 += r[e+1]; s2 += r[e+2]; s3 += r[e+3];
            }
            g_pooled1[(size_t)q * P1_RPB + tid] =
                ((s0 + s1) + (s2 + s3) + r[48]) * (1.0f / 49.0f);
        }
        __syncthreads();
        if (tid == 0) {
            __threadfence();
            atomicAdd(&g_cnt1[q >> 7], 1u);
        }
    } else if (bx >= PB0) {
        // ---- pool0 block: warp per (b,c) row, 8 rows ----
        const unsigned p = bx - PB0;
        const unsigned wid  = (p * 256u + tid) >> 5;
        const unsigned lane = tid & 31u;
        const float4* src = reinterpret_cast<const float4*>(feat0) + (size_t)wid * 49;
        float4 a = __ldcs(src + lane);
        float  s = (a.x + a.y) + (a.z + a.w);
        if (lane < 17u) {
            float4 c = __ldcs(src + 32u + lane);
            s += (c.x + c.y) + (c.z + c.w);
        }
        #pragma unroll
        for (int o = 16; o; o >>= 1) s += __shfl_xor_sync(0xffffffffu, s, o);
        if (lane == 0u) g_pooled0[wid] = s * (1.0f / 196.0f);
        __syncthreads();
        if (tid == 0) {
            __threadfence();
            atomicAdd(&g_cnt0[p >> 10], 1u);
        }
    } else {
        // ---- head blocks (resident from wave 1, doorbell-gated) ----
        if (bx < HB1) {
            const int t = bx - HB0;
            wait_cnt(&g_cnt0[t], 1024u);
            head_tile<C0_, K0_, KP0, 2, PITCH0, 0>(
                g_pooled0, W0, b0v, lut0, cw0, target, t * MB, sraw);
        } else {
            const int t = bx - HB1;
            wait_cnt(&g_cnt1[t], 128u);
            head_tile<C1_, K1_, KP1, 1, PITCH1, 2>(
                g_pooled1, W1, b1v, lut1, cw1, target, t * MB, sraw);
        }
        // finalize: last head block computes out and resets all state
        if (tid == 0) {
            __threadfence();
            const unsigned arrived = atomicAdd(&g_done, 1u);
            if (arrived == 127u) {
                const float n0 = atomicAdd(&g_accum[0], 0.0f);
                const float d0 = atomicAdd(&g_accum[1], 0.0f);
                const float n1 = atomicAdd(&g_accum[2], 0.0f);
                const float d1 = atomicAdd(&g_accum[3], 0.0f);
                out[0] = n0 / d0 + n1 / d1;
                #pragma unroll
                for (int i = 0; i < 4; i++) atomicExch(&g_accum[i], 0.0f);
                for (int i = 0; i < NT0; i++) atomicExch(&g_cnt0[i], 0u);
                for (int i = 0; i < NT1; i++) atomicExch(&g_cnt1[i], 0u);
                __threadfence();
                atomicExch(&g_done, 0u);
            }
        }
    }
}

// ---------------- launch ----------------
extern "C" void kernel_launch(void* const* d_in, const int* in_sizes, int n_in,
                              void* d_out, int out_size) {
    (void)in_sizes; (void)n_in; (void)out_size;
    const float* feat0  = (const float*)d_in[0];
    const float* feat1  = (const float*)d_in[1];
    const float* W0     = (const float*)d_in[2];
    const float* b0v    = (const float*)d_in[3];
    const float* W1     = (const float*)d_in[4];
    const float* b1v    = (const float*)d_in[5];
    const int*   lut0   = (const int*)d_in[6];
    const int*   lut1   = (const int*)d_in[7];
    const float* cw0    = (const float*)d_in[8];
    const float* cw1    = (const float*)d_in[9];
    const int*   target = (const int*)d_in[10];
    float* out = (float*)d_out;

    mega_kernel<<<NBLKS, 256>>>(feat0, feat1, W0, b0v, W1, b1v,
                                lut0, lut1, cw0, cw1, target, out);
}

// round 10
// speedup vs baseline: 1.6266x; 1.6266x over previous
#include <cuda_runtime.h>

// ---------------- problem constants ----------------
#define BATCH 1024
#define C0_ 512
#define C1_ 1024
#define K0_ 100
#define K1_ 50
#define KP0 128
#define KP1 64
#define ROWS0 (BATCH*C0_)   // 524288
#define ROWS1 (BATCH*C1_)   // 1048576

#define MB 16
#define CC 64
#define PITCH0 133          // odd: conflict-free transposed STS + LDS
#define PITCH1 69

// ---------------- scratch ----------------
__device__ float    g_pooled0[ROWS0];
__device__ float    g_pooled1[ROWS1];
__device__ float    g_accum[4] = {0.f, 0.f, 0.f, 0.f};
__device__ unsigned g_done = 0u;

// ---------------- fused pooling (R8-proven, at HBM ceiling) ----------------
#define NB0 ((ROWS0*32)/256)    // 65536
#define P1_RPB 128
#define P1_FLT (P1_RPB*49)      // 6272
#define P1_VEC (P1_FLT/4)       // 1568
#define NB1 (ROWS1/P1_RPB)      // 8192

__global__ void __launch_bounds__(256)
pool_kernel(const float* __restrict__ feat0, const float* __restrict__ feat1) {
    __shared__ float sf[P1_FLT];
    if (blockIdx.x == 0 && threadIdx.x < 5) {
        if (threadIdx.x < 4) g_accum[threadIdx.x] = 0.0f;
        else g_done = 0u;
    }
    if (blockIdx.x < NB0) {
        const unsigned wid  = (blockIdx.x * 256u + threadIdx.x) >> 5;
        const unsigned lane = threadIdx.x & 31u;
        const float4* src = reinterpret_cast<const float4*>(feat0) + (size_t)wid * 49;
        float4 a = __ldcs(src + lane);
        float  s = (a.x + a.y) + (a.z + a.w);
        if (lane < 17u) {
            float4 c = __ldcs(src + 32u + lane);
            s += (c.x + c.y) + (c.z + c.w);
        }
        #pragma unroll
        for (int o = 16; o; o >>= 1) s += __shfl_xor_sync(0xffffffffu, s, o);
        if (lane == 0u) g_pooled0[wid] = s * (1.0f / 196.0f);
    } else {
        const unsigned blk = blockIdx.x - NB0;
        const float4* src = reinterpret_cast<const float4*>(feat1) + (size_t)blk * P1_VEC;
        float4* dst = reinterpret_cast<float4*>(sf);
        #pragma unroll 4
        for (int i = threadIdx.x; i < P1_VEC; i += 256)
            dst[i] = __ldcs(src + i);
        __syncthreads();
        const int t = threadIdx.x;
        if (t < P1_RPB) {
            const float* r = sf + t * 49;
            float s0 = 0.f, s1 = 0.f, s2 = 0.f, s3 = 0.f;
            #pragma unroll
            for (int e = 0; e < 48; e += 4) {
                s0 += r[e]; s1 += r[e+1]; s2 += r[e+2]; s3 += r[e+3];
            }
            g_pooled1[(size_t)blk * P1_RPB + t] =
                ((s0 + s1) + (s2 + s3) + r[48]) * (1.0f / 49.0f);
        }
    }
}

// ---------------- head tile v3: 512 thr, pipelined W tiles ------------------
// smem: sp[MB*C] | swt[2][CC][PITCH] | slg[MB][PITCH]
// head0: 32768 + 68096 + 8512 = 109376 B ; head1: 65536 + 35328 + 4416 = 105280 B
#define HEAD_SMEM 109376

template<int C, int K, int KPAD, int TK, int PITCH, int AOFF>
__device__ __forceinline__ void head_tile(
    const float* __restrict__ pooled,
    const float* __restrict__ W, const float* __restrict__ bias,
    const int* __restrict__ lut, const float* __restrict__ cw,
    const int* __restrict__ target, int m0, char* sraw)
{
    float* sp = reinterpret_cast<float*>(sraw);                       // [MB*C]
    float (*swt)[CC][PITCH] =
        reinterpret_cast<float(*)[CC][PITCH]>(sraw + 4*MB*C);
    float (*slg)[PITCH] =
        reinterpret_cast<float(*)[PITCH]>(sraw + 4*(MB*C + 2*CC*PITCH));

    const int tid = threadIdx.x;

    // stage pooled tile once: contiguous MB*C floats
    {
        const float4* src = reinterpret_cast<const float4*>(pooled + (size_t)m0 * C);
        float4* dst = reinterpret_cast<float4*>(sp);
        #pragma unroll
        for (int i = tid; i < MB * C / 4; i += 512) dst[i] = src[i];
    }

    constexpr int NLD = KPAD * CC / 512;   // 16 (head0) / 8 (head1)
    float ld[NLD];

    // prologue: tile 0
    #pragma unroll
    for (int j = 0; j < NLD; j++) {
        const int idx = tid + j * 512;
        const int c = idx & (CC - 1), k = idx >> 6;
        ld[j] = (k < K) ? W[(size_t)k * C + c] : 0.0f;
    }
    #pragma unroll
    for (int j = 0; j < NLD; j++) {
        const int idx = tid + j * 512;
        swt[0][idx & (CC - 1)][idx >> 6] = ld[j];
    }
    __syncthreads();

    const int ktg = tid & 63;     // k-group
    const int bt  = tid >> 6;     // 8 b-groups x 2 rows
    float acc[2][TK];
    #pragma unroll
    for (int j = 0; j < 2; j++)
        #pragma unroll
        for (int t = 0; t < TK; t++) acc[j][t] = 0.0f;

    constexpr int NCH = C / CC;
    #pragma unroll 1
    for (int ch = 0; ch < NCH; ch++) {
        // issue next tile's LDGs (latency overlapped with compute below)
        if (ch + 1 < NCH) {
            const int c0 = (ch + 1) * CC;
            #pragma unroll
            for (int j = 0; j < NLD; j++) {
                const int idx = tid + j * 512;
                const int c = idx & (CC - 1), k = idx >> 6;
                ld[j] = (k < K) ? W[(size_t)k * C + c0 + c] : 0.0f;
            }
        }
        // compute current chunk from smem
        const float* sp0 = sp + (bt * 2 + 0) * C + ch * CC;
        const float* sp1 = sp + (bt * 2 + 1) * C + ch * CC;
        const float (*wt)[PITCH] = swt[ch & 1];
        #pragma unroll
        for (int c = 0; c < CC; c++) {
            const float p0 = sp0[c], p1 = sp1[c];
            if (TK == 2) {
                const float w0 = wt[c][ktg];
                const float w1 = wt[c][ktg + 64];
                acc[0][0] = fmaf(p0, w0, acc[0][0]);
                acc[0][1] = fmaf(p0, w1, acc[0][1]);
                acc[1][0] = fmaf(p1, w0, acc[1][0]);
                acc[1][1] = fmaf(p1, w1, acc[1][1]);
            } else {
                const float w0 = wt[c][ktg];
                acc[0][0] = fmaf(p0, w0, acc[0][0]);
                acc[1][0] = fmaf(p1, w0, acc[1][0]);
            }
        }
        // store next tile into the other buffer
        if (ch + 1 < NCH) {
            #pragma unroll
            for (int j = 0; j < NLD; j++) {
                const int idx = tid + j * 512;
                swt[(ch + 1) & 1][idx & (CC - 1)][idx >> 6] = ld[j];
            }
        }
        __syncthreads();
    }

    // logits -> smem
    #pragma unroll
    for (int t = 0; t < TK; t++) {
        const int k = ktg + t * 64;
        const float bv = (k < K) ? bias[k] : 0.0f;
        slg[bt * 2 + 0][k] = acc[0][t] + bv;
        slg[bt * 2 + 1][k] = acc[1][t] + bv;
    }
    __syncthreads();

    // softmax-CE: 16 warps, one per row
    const int w = tid >> 5, lane = tid & 31;
    {
        float m = -3.4e38f;
        for (int k = lane; k < K; k += 32) m = fmaxf(m, slg[w][k]);
        #pragma unroll
        for (int o = 16; o; o >>= 1) m = fmaxf(m, __shfl_xor_sync(0xffffffffu, m, o));
        float s = 0.0f;
        for (int k = lane; k < K; k += 32) s += __expf(slg[w][k] - m);
        #pragma unroll
        for (int o = 16; o; o >>= 1) s += __shfl_xor_sync(0xffffffffu, s, o);
        if (lane == 0) {
            const int t = lut[target[m0 + w]];
            const float nll = m + __logf(s) - slg[w][t];
            const float wt  = cw[t];
            atomicAdd(&g_accum[AOFF],     wt * nll);
            atomicAdd(&g_accum[AOFF + 1], wt);
        }
    }
    __syncthreads();
}

// heads + in-kernel finalize (last block computes out[0], resets state)
__global__ void __launch_bounds__(512)
heads_kernel(const float* __restrict__ W0, const float* __restrict__ b0v,
             const int* __restrict__ lut0, const float* __restrict__ cw0,
             const float* __restrict__ W1, const float* __restrict__ b1v,
             const int* __restrict__ lut1, const float* __restrict__ cw1,
             const int* __restrict__ target, float* __restrict__ out)
{
    extern __shared__ __align__(16) char sraw[];
    const unsigned nblocks = 2u * (BATCH / MB);   // 128
    if (blockIdx.x < BATCH / MB)
        head_tile<C0_, K0_, KP0, 2, PITCH0, 0>(
            g_pooled0, W0, b0v, lut0, cw0, target, blockIdx.x * MB, sraw);
    else
        head_tile<C1_, K1_, KP1, 1, PITCH1, 2>(
            g_pooled1, W1, b1v, lut1, cw1, target,
            (blockIdx.x - BATCH / MB) * MB, sraw);

    if (threadIdx.x == 0) {
        __threadfence();
        const unsigned arrived = atomicAdd(&g_done, 1u);
        if (arrived == nblocks - 1u) {
            const float n0 = atomicAdd(&g_accum[0], 0.0f);
            const float d0 = atomicAdd(&g_accum[1], 0.0f);
            const float n1 = atomicAdd(&g_accum[2], 0.0f);
            const float d1 = atomicAdd(&g_accum[3], 0.0f);
            out[0] = n0 / d0 + n1 / d1;
            #pragma unroll
            for (int i = 0; i < 4; i++) atomicExch(&g_accum[i], 0.0f);
            __threadfence();
            atomicExch(&g_done, 0u);
        }
    }
}

// ---------------- launch ----------------
extern "C" void kernel_launch(void* const* d_in, const int* in_sizes, int n_in,
                              void* d_out, int out_size) {
    (void)in_sizes; (void)n_in; (void)out_size;
    const float* feat0  = (const float*)d_in[0];
    const float* feat1  = (const float*)d_in[1];
    const float* W0     = (const float*)d_in[2];
    const float* b0v    = (const float*)d_in[3];
    const float* W1     = (const float*)d_in[4];
    const float* b1v    = (const float*)d_in[5];
    const int*   lut0   = (const int*)d_in[6];
    const int*   lut1   = (const int*)d_in[7];
    const float* cw0    = (const float*)d_in[8];
    const float* cw1    = (const float*)d_in[9];
    const int*   target = (const int*)d_in[10];
    float* out = (float*)d_out;

    cudaFuncSetAttribute(heads_kernel,
                         cudaFuncAttributeMaxDynamicSharedMemorySize, HEAD_SMEM);

    pool_kernel<<<NB0 + NB1, 256>>>(feat0, feat1);
    heads_kernel<<<2 * (BATCH / MB), 512, HEAD_SMEM>>>(
        W0, b0v, lut0, cw0, W1, b1v, lut1, cw1, target, out);
}